// round 1
// baseline (speedup 1.0000x reference)
#include <cuda_runtime.h>
#include <math.h>

// Problem constants
#define NTOK   8192      // B*N = 8*1024
#define DMODEL 128
#define NHEADS 8
#define HDIM   128
#define INNER  1024      // NHEADS*HDIM
#define QKVC   3072      // 3*INNER
#define SEQ    1024
#define BATCH  8

// Scratch buffers (no allocation allowed -> device globals)
__device__ float g_qkv[(size_t)NTOK * QKVC];   // 96 MB
__device__ float g_z[(size_t)NTOK * INNER];    // 32 MB

// ---------------------------------------------------------------------------
// Generic tiled SGEMM: C[M,N] = A[M,K] @ B[K,N] (+bias[N]), all row-major.
// Requires M%BM==0, N%BN==0, K%BK==0 (true for all our shapes).
// ---------------------------------------------------------------------------
template<int BM, int BN, int BK, int TM, int TN>
__global__ void sgemm_kernel(const float* __restrict__ A,
                             const float* __restrict__ B,
                             float* __restrict__ C,
                             const float* __restrict__ bias,
                             int M, int N, int K)
{
    constexpr int TX = BN / TN;
    constexpr int TY = BM / TM;
    constexpr int NT = TX * TY;           // threads per block

    __shared__ float As[BM][BK];
    __shared__ float Bs[BK][BN];

    const int tid = threadIdx.x;
    const int tx  = tid % TX;
    const int ty  = tid / TX;
    const int m0  = blockIdx.y * BM;
    const int n0  = blockIdx.x * BN;

    float acc[TM][TN];
#pragma unroll
    for (int i = 0; i < TM; i++)
#pragma unroll
        for (int j = 0; j < TN; j++) acc[i][j] = 0.0f;

    for (int k0 = 0; k0 < K; k0 += BK) {
        // load A tile
        constexpr int AF4 = BM * BK / 4;
#pragma unroll
        for (int f = 0; f < AF4 / NT; f++) {
            int idx = tid + f * NT;
            int row = idx / (BK / 4);
            int c4  = idx % (BK / 4);
            float4 v = *reinterpret_cast<const float4*>(
                A + (size_t)(m0 + row) * K + k0 + 4 * c4);
            *reinterpret_cast<float4*>(&As[row][4 * c4]) = v;
        }
        // load B tile
        constexpr int BF4 = BK * BN / 4;
#pragma unroll
        for (int f = 0; f < BF4 / NT; f++) {
            int idx = tid + f * NT;
            int row = idx / (BN / 4);
            int c4  = idx % (BN / 4);
            float4 v = *reinterpret_cast<const float4*>(
                B + (size_t)(k0 + row) * N + n0 + 4 * c4);
            *reinterpret_cast<float4*>(&Bs[row][4 * c4]) = v;
        }
        __syncthreads();

#pragma unroll 8
        for (int k = 0; k < BK; k++) {
            float a[TM], bv[TN];
#pragma unroll
            for (int i = 0; i < TM; i++) a[i] = As[ty * TM + i][k];
#pragma unroll
            for (int j4 = 0; j4 < TN / 4; j4++) {
                float4 v = *reinterpret_cast<const float4*>(&Bs[k][tx * TN + 4 * j4]);
                bv[4 * j4 + 0] = v.x; bv[4 * j4 + 1] = v.y;
                bv[4 * j4 + 2] = v.z; bv[4 * j4 + 3] = v.w;
            }
#pragma unroll
            for (int i = 0; i < TM; i++)
#pragma unroll
                for (int j = 0; j < TN; j++)
                    acc[i][j] = fmaf(a[i], bv[j], acc[i][j]);
        }
        __syncthreads();
    }

    // epilogue
#pragma unroll
    for (int i = 0; i < TM; i++) {
        const size_t row = (size_t)(m0 + ty * TM + i);
#pragma unroll
        for (int j4 = 0; j4 < TN / 4; j4++) {
            const int col = n0 + tx * TN + 4 * j4;
            float4 v;
            v.x = acc[i][4 * j4 + 0];
            v.y = acc[i][4 * j4 + 1];
            v.z = acc[i][4 * j4 + 2];
            v.w = acc[i][4 * j4 + 3];
            if (bias) {
                v.x += bias[col + 0];
                v.y += bias[col + 1];
                v.z += bias[col + 2];
                v.w += bias[col + 3];
            }
            *reinterpret_cast<float4*>(C + row * N + col) = v;
        }
    }
}

// ---------------------------------------------------------------------------
// Flash attention. One block handles 64 query rows of one (b, h).
// qkv layout: [8192][3072] with Q cols [0,1024), K [1024,2048), V [2048,3072),
// head h occupying cols h*128..h*128+127 of each section.
// Output z: [8192][1024] row-major (b,n major), col = h*128 + d.
// 256 threads: tx=tid&15 (S cols / O cols), ty=tid>>4 (S rows).
// Per thread: 4x4 S fragment, 4x8 O fragment.
// ---------------------------------------------------------------------------
#define KT_STRIDE 65
#define ATT_SMEM_FLOATS (64 * 128 + 128 * KT_STRIDE + 64 * 128 + 64 * 64)
#define ATT_SMEM_BYTES  (ATT_SMEM_FLOATS * 4)

__global__ void attn_kernel(const float* __restrict__ qkv, float* __restrict__ z)
{
    extern __shared__ float sm[];
    float* Qs = sm;                         // [64][128]
    float* Kt = Qs + 64 * 128;              // [128][KT_STRIDE] (k-major, transposed)
    float* Vs = Kt + 128 * KT_STRIDE;       // [64][128]
    float* Ps = Vs + 64 * 128;              // [64][64]

    const int tid = threadIdx.x;
    const int tx  = tid & 15;
    const int ty  = tid >> 4;
    const int qt  = blockIdx.x;
    const int h   = blockIdx.y;
    const int b   = blockIdx.z;

    const int n0 = qt * 64;
    const float scale = 0.08838834764831845f;   // 1/sqrt(128)

    const float* qbase = qkv + (size_t)(b * SEQ + n0) * QKVC + h * HDIM;
    const float* kbase = qkv + (size_t)(b * SEQ) * QKVC + INNER + h * HDIM;
    const float* vbase = kbase + INNER;

    // load Q tile (pre-scaled)
    for (int f = tid; f < 2048; f += 256) {
        int row = f >> 5;
        int c4  = f & 31;
        float4 v = *reinterpret_cast<const float4*>(qbase + (size_t)row * QKVC + 4 * c4);
        v.x *= scale; v.y *= scale; v.z *= scale; v.w *= scale;
        reinterpret_cast<float4*>(Qs)[row * 32 + c4] = v;
    }

    const int r0 = ty * 4;
    const int c0 = tx * 4;
    const int d0 = tx * 8;

    float m_i[4] = {-1e30f, -1e30f, -1e30f, -1e30f};
    float l_i[4] = {0.f, 0.f, 0.f, 0.f};
    float o[4][8];
#pragma unroll
    for (int i = 0; i < 4; i++)
#pragma unroll
        for (int c = 0; c < 8; c++) o[i][c] = 0.f;

    for (int j0 = 0; j0 < SEQ; j0 += 64) {
        __syncthreads();   // protect Kt/Vs/Ps reuse across iterations
        // load K (transposed into Kt) and V tiles
        for (int f = tid; f < 2048; f += 256) {
            int row = f >> 5;
            int c4  = f & 31;
            float4 kv = *reinterpret_cast<const float4*>(
                kbase + (size_t)(j0 + row) * QKVC + 4 * c4);
            Kt[(4 * c4 + 0) * KT_STRIDE + row] = kv.x;
            Kt[(4 * c4 + 1) * KT_STRIDE + row] = kv.y;
            Kt[(4 * c4 + 2) * KT_STRIDE + row] = kv.z;
            Kt[(4 * c4 + 3) * KT_STRIDE + row] = kv.w;
            float4 vv = *reinterpret_cast<const float4*>(
                vbase + (size_t)(j0 + row) * QKVC + 4 * c4);
            reinterpret_cast<float4*>(Vs)[row * 32 + c4] = vv;
        }
        __syncthreads();

        // S = Q @ K^T   (scale folded into Q)
        float s[4][4];
#pragma unroll
        for (int i = 0; i < 4; i++)
#pragma unroll
            for (int j = 0; j < 4; j++) s[i][j] = 0.f;

#pragma unroll 8
        for (int k = 0; k < 128; k++) {
            float q[4], kk[4];
#pragma unroll
            for (int i = 0; i < 4; i++) q[i] = Qs[(r0 + i) * 128 + k];
#pragma unroll
            for (int j = 0; j < 4; j++) kk[j] = Kt[k * KT_STRIDE + c0 + j];
#pragma unroll
            for (int i = 0; i < 4; i++)
#pragma unroll
                for (int j = 0; j < 4; j++)
                    s[i][j] = fmaf(q[i], kk[j], s[i][j]);
        }

        // online softmax update (rows split across 16 lanes of a half-warp)
#pragma unroll
        for (int i = 0; i < 4; i++) {
            float rm = fmaxf(fmaxf(s[i][0], s[i][1]), fmaxf(s[i][2], s[i][3]));
            rm = fmaxf(rm, __shfl_xor_sync(0xffffffffu, rm, 1));
            rm = fmaxf(rm, __shfl_xor_sync(0xffffffffu, rm, 2));
            rm = fmaxf(rm, __shfl_xor_sync(0xffffffffu, rm, 4));
            rm = fmaxf(rm, __shfl_xor_sync(0xffffffffu, rm, 8));
            float mn = fmaxf(m_i[i], rm);
            float alpha = __expf(m_i[i] - mn);
            float p0 = __expf(s[i][0] - mn);
            float p1 = __expf(s[i][1] - mn);
            float p2 = __expf(s[i][2] - mn);
            float p3 = __expf(s[i][3] - mn);
            float rs = p0 + p1 + p2 + p3;
            rs += __shfl_xor_sync(0xffffffffu, rs, 1);
            rs += __shfl_xor_sync(0xffffffffu, rs, 2);
            rs += __shfl_xor_sync(0xffffffffu, rs, 4);
            rs += __shfl_xor_sync(0xffffffffu, rs, 8);
            l_i[i] = alpha * l_i[i] + rs;
            m_i[i] = mn;
#pragma unroll
            for (int c = 0; c < 8; c++) o[i][c] *= alpha;
            *reinterpret_cast<float4*>(&Ps[(r0 + i) * 64 + c0]) =
                make_float4(p0, p1, p2, p3);
        }
        __syncthreads();

        // O += P @ V
#pragma unroll 4
        for (int j = 0; j < 64; j++) {
            float p[4];
#pragma unroll
            for (int i = 0; i < 4; i++) p[i] = Ps[(r0 + i) * 64 + j];
            float4 va = reinterpret_cast<float4*>(Vs)[j * 32 + 2 * tx];
            float4 vb = reinterpret_cast<float4*>(Vs)[j * 32 + 2 * tx + 1];
#pragma unroll
            for (int i = 0; i < 4; i++) {
                o[i][0] = fmaf(p[i], va.x, o[i][0]);
                o[i][1] = fmaf(p[i], va.y, o[i][1]);
                o[i][2] = fmaf(p[i], va.z, o[i][2]);
                o[i][3] = fmaf(p[i], va.w, o[i][3]);
                o[i][4] = fmaf(p[i], vb.x, o[i][4]);
                o[i][5] = fmaf(p[i], vb.y, o[i][5]);
                o[i][6] = fmaf(p[i], vb.z, o[i][6]);
                o[i][7] = fmaf(p[i], vb.w, o[i][7]);
            }
        }
    }

    // normalize + write z
#pragma unroll
    for (int i = 0; i < 4; i++) {
        float inv = 1.0f / l_i[i];
        size_t row = (size_t)(b * SEQ + n0 + r0 + i);
        float* dst = z + row * INNER + h * HDIM + d0;
        float4 a, c;
        a.x = o[i][0] * inv; a.y = o[i][1] * inv;
        a.z = o[i][2] * inv; a.w = o[i][3] * inv;
        c.x = o[i][4] * inv; c.y = o[i][5] * inv;
        c.z = o[i][6] * inv; c.w = o[i][7] * inv;
        *reinterpret_cast<float4*>(dst + 0) = a;
        *reinterpret_cast<float4*>(dst + 4) = c;
    }
}

// ---------------------------------------------------------------------------
// Launch
// ---------------------------------------------------------------------------
extern "C" void kernel_launch(void* const* d_in, const int* in_sizes, int n_in,
                              void* d_out, int out_size)
{
    const float* x     = (const float*)d_in[0];   // [8,1024,128]
    const float* w_qkv = (const float*)d_in[1];   // [128,3072]
    const float* w_out = (const float*)d_in[2];   // [1024,128]
    const float* b_out = (const float*)d_in[3];   // [128]
    float* out = (float*)d_out;                   // [8,1024,128]

    void* qkvp = nullptr;
    void* zp   = nullptr;
    cudaGetSymbolAddress(&qkvp, g_qkv);
    cudaGetSymbolAddress(&zp, g_z);
    float* qkv = (float*)qkvp;
    float* zb  = (float*)zp;

    // 1) QKV projection: [8192,128] @ [128,3072]
    {
        dim3 grid(QKVC / 128, NTOK / 128);
        sgemm_kernel<128, 128, 32, 8, 8><<<grid, 256>>>(
            x, w_qkv, qkv, nullptr, NTOK, QKVC, DMODEL);
    }

    // 2) attention
    {
        cudaFuncSetAttribute(attn_kernel,
                             cudaFuncAttributeMaxDynamicSharedMemorySize,
                             ATT_SMEM_BYTES);
        dim3 grid(SEQ / 64, NHEADS, BATCH);
        attn_kernel<<<grid, 256, ATT_SMEM_BYTES>>>(qkv, zb);
    }

    // 3) output projection: [8192,1024] @ [1024,128] + bias
    {
        dim3 grid(DMODEL / 64, NTOK / 64);
        sgemm_kernel<64, 64, 64, 4, 4><<<grid, 256>>>(
            zb, w_out, out, b_out, NTOK, DMODEL, INNER);
    }
}

// round 4
// speedup vs baseline: 2.2572x; 2.2572x over previous
#include <cuda_runtime.h>
#include <math.h>
#include <stdint.h>

// Problem constants
#define NTOK   8192      // B*N = 8*1024
#define DMODEL 128
#define NHEADS 8
#define HDIM   128
#define INNER  1024      // NHEADS*HDIM
#define QKVC   3072      // 3*INNER
#define SEQ    1024
#define BATCH  8

// Scratch buffers (no allocation allowed -> device globals)
__device__ float g_qkv[(size_t)NTOK * QKVC];   // 96 MB
__device__ float g_z[(size_t)NTOK * INNER];    // 32 MB

// ---------------------------------------------------------------------------
// Generic tiled SGEMM (fp32): C[M,N] = A[M,K] @ B[K,N] (+bias[N]), row-major.
// Kept fp32 for precision headroom (qkv + out projections).
// ---------------------------------------------------------------------------
template<int BM, int BN, int BK, int TM, int TN>
__global__ void sgemm_kernel(const float* __restrict__ A,
                             const float* __restrict__ B,
                             float* __restrict__ C,
                             const float* __restrict__ bias,
                             int M, int N, int K)
{
    constexpr int TX = BN / TN;
    constexpr int TY = BM / TM;
    constexpr int NT = TX * TY;

    __shared__ float As[BM][BK];
    __shared__ float Bs[BK][BN];

    const int tid = threadIdx.x;
    const int tx  = tid % TX;
    const int ty  = tid / TX;
    const int m0  = blockIdx.y * BM;
    const int n0  = blockIdx.x * BN;

    float acc[TM][TN];
#pragma unroll
    for (int i = 0; i < TM; i++)
#pragma unroll
        for (int j = 0; j < TN; j++) acc[i][j] = 0.0f;

    for (int k0 = 0; k0 < K; k0 += BK) {
        constexpr int AF4 = BM * BK / 4;
#pragma unroll
        for (int f = 0; f < AF4 / NT; f++) {
            int idx = tid + f * NT;
            int row = idx / (BK / 4);
            int c4  = idx % (BK / 4);
            float4 v = *reinterpret_cast<const float4*>(
                A + (size_t)(m0 + row) * K + k0 + 4 * c4);
            *reinterpret_cast<float4*>(&As[row][4 * c4]) = v;
        }
        constexpr int BF4 = BK * BN / 4;
#pragma unroll
        for (int f = 0; f < BF4 / NT; f++) {
            int idx = tid + f * NT;
            int row = idx / (BN / 4);
            int c4  = idx % (BN / 4);
            float4 v = *reinterpret_cast<const float4*>(
                B + (size_t)(k0 + row) * N + n0 + 4 * c4);
            *reinterpret_cast<float4*>(&Bs[row][4 * c4]) = v;
        }
        __syncthreads();

#pragma unroll 8
        for (int k = 0; k < BK; k++) {
            float a[TM], bv[TN];
#pragma unroll
            for (int i = 0; i < TM; i++) a[i] = As[ty * TM + i][k];
#pragma unroll
            for (int j4 = 0; j4 < TN / 4; j4++) {
                float4 v = *reinterpret_cast<const float4*>(&Bs[k][tx * TN + 4 * j4]);
                bv[4 * j4 + 0] = v.x; bv[4 * j4 + 1] = v.y;
                bv[4 * j4 + 2] = v.z; bv[4 * j4 + 3] = v.w;
            }
#pragma unroll
            for (int i = 0; i < TM; i++)
#pragma unroll
                for (int j = 0; j < TN; j++)
                    acc[i][j] = fmaf(a[i], bv[j], acc[i][j]);
        }
        __syncthreads();
    }

#pragma unroll
    for (int i = 0; i < TM; i++) {
        const size_t row = (size_t)(m0 + ty * TM + i);
#pragma unroll
        for (int j4 = 0; j4 < TN / 4; j4++) {
            const int col = n0 + tx * TN + 4 * j4;
            float4 v;
            v.x = acc[i][4 * j4 + 0];
            v.y = acc[i][4 * j4 + 1];
            v.z = acc[i][4 * j4 + 2];
            v.w = acc[i][4 * j4 + 3];
            if (bias) {
                v.x += bias[col + 0];
                v.y += bias[col + 1];
                v.z += bias[col + 2];
                v.w += bias[col + 3];
            }
            *reinterpret_cast<float4*>(C + row * N + col) = v;
        }
    }
}

// ---------------------------------------------------------------------------
// tf32 mma.sync helpers
// ---------------------------------------------------------------------------
__device__ __forceinline__ uint32_t f2tf32(float x) {
    uint32_t u;
    asm("cvt.rna.tf32.f32 %0, %1;" : "=r"(u) : "f"(x));
    return u;
}

__device__ __forceinline__ void mma_tf32(float* c, const uint32_t* a,
                                         uint32_t b0, uint32_t b1) {
    asm volatile(
        "mma.sync.aligned.m16n8k8.row.col.f32.tf32.tf32.f32 "
        "{%0,%1,%2,%3},{%4,%5,%6,%7},{%8,%9},{%0,%1,%2,%3};"
        : "+f"(c[0]), "+f"(c[1]), "+f"(c[2]), "+f"(c[3])
        : "r"(a[0]), "r"(a[1]), "r"(a[2]), "r"(a[3]), "r"(b0), "r"(b1));
}

// ---------------------------------------------------------------------------
// Flash attention on tensor cores (tf32, fp32 accumulate).
// Block: 128 threads (4 warps), 64 query rows of one (b, h). KV tile = 64.
// Warp w owns q rows [w*16, w*16+16).
//   S = Q @ K^T : A = Q (in registers, loaded once), B = K tile (smem).
//   P @ V       : A = P (smem round-trip, tf32),   B = V tile (smem).
// Strides: Ks 132, Vs 136, Ps 68 -> all fragment LDS conflict-free.
// ---------------------------------------------------------------------------
#define KS_STRIDE 132
#define VS_STRIDE 136
#define PS_STRIDE 68
#define ATT_SMEM_U32 (64 * KS_STRIDE + 64 * VS_STRIDE + 64 * PS_STRIDE)
#define ATT_SMEM_BYTES (ATT_SMEM_U32 * 4)

__global__ __launch_bounds__(128)
void attn_tc_kernel(const float* __restrict__ qkv, float* __restrict__ z)
{
    extern __shared__ uint32_t sm[];
    uint32_t* Ks = sm;                              // [64][132]
    uint32_t* Vs = sm + 64 * KS_STRIDE;             // [64][136]
    uint32_t* Ps = Vs + 64 * VS_STRIDE;             // [64][68]

    const int tid  = threadIdx.x;
    const int w    = tid >> 5;
    const int lane = tid & 31;
    const int g    = lane >> 2;   // 0..7
    const int tig  = lane & 3;    // 0..3

    const int qt = blockIdx.x;
    const int h  = blockIdx.y;
    const int b  = blockIdx.z;
    const int n0 = qt * 64;

    const float scale = 0.08838834764831845f;   // 1/sqrt(128)

    const float* qbase = qkv + (size_t)(b * SEQ + n0) * QKVC + h * HDIM;
    const float* kbase = qkv + (size_t)(b * SEQ) * QKVC + INNER + h * HDIM;
    const float* vbase = kbase + INNER;

    // ---- stage Q (scaled, tf32) via Vs, then pull A-fragments to registers
    for (int f = tid; f < 2048; f += 128) {
        int row = f >> 5;
        int c4  = f & 31;
        float4 v = *reinterpret_cast<const float4*>(qbase + (size_t)row * QKVC + 4 * c4);
        uint4 u;
        u.x = f2tf32(v.x * scale);
        u.y = f2tf32(v.y * scale);
        u.z = f2tf32(v.z * scale);
        u.w = f2tf32(v.w * scale);
        *reinterpret_cast<uint4*>(Vs + row * VS_STRIDE + 4 * c4) = u;
    }
    __syncthreads();

    const int r_lo = w * 16 + g;     // block-local q row (low half)
    uint32_t qa[16][4];
#pragma unroll
    for (int ks = 0; ks < 16; ks++) {
        qa[ks][0] = Vs[r_lo * VS_STRIDE + ks * 8 + tig];
        qa[ks][1] = Vs[(r_lo + 8) * VS_STRIDE + ks * 8 + tig];
        qa[ks][2] = Vs[r_lo * VS_STRIDE + ks * 8 + tig + 4];
        qa[ks][3] = Vs[(r_lo + 8) * VS_STRIDE + ks * 8 + tig + 4];
    }

    float oacc[16][4];
#pragma unroll
    for (int nf = 0; nf < 16; nf++)
#pragma unroll
        for (int c = 0; c < 4; c++) oacc[nf][c] = 0.0f;
    float m0 = -1e30f, m1 = -1e30f, l0 = 0.0f, l1 = 0.0f;

    for (int j0 = 0; j0 < SEQ; j0 += 64) {
        __syncthreads();   // previous iteration finished reading Ks/Vs
        for (int f = tid; f < 2048; f += 128) {
            int row = f >> 5;
            int c4  = f & 31;
            float4 kv = *reinterpret_cast<const float4*>(
                kbase + (size_t)(j0 + row) * QKVC + 4 * c4);
            uint4 ku;
            ku.x = f2tf32(kv.x); ku.y = f2tf32(kv.y);
            ku.z = f2tf32(kv.z); ku.w = f2tf32(kv.w);
            *reinterpret_cast<uint4*>(Ks + row * KS_STRIDE + 4 * c4) = ku;
            float4 vv = *reinterpret_cast<const float4*>(
                vbase + (size_t)(j0 + row) * QKVC + 4 * c4);
            uint4 vu;
            vu.x = f2tf32(vv.x); vu.y = f2tf32(vv.y);
            vu.z = f2tf32(vv.z); vu.w = f2tf32(vv.w);
            *reinterpret_cast<uint4*>(Vs + row * VS_STRIDE + 4 * c4) = vu;
        }
        __syncthreads();

        // ---- S = Q @ K^T (64x64 per block, 16x64 per warp)
        float sacc[8][4];
#pragma unroll
        for (int nf = 0; nf < 8; nf++)
#pragma unroll
            for (int c = 0; c < 4; c++) sacc[nf][c] = 0.0f;

#pragma unroll
        for (int ks = 0; ks < 16; ks++) {
#pragma unroll
            for (int nf = 0; nf < 8; nf++) {
                uint32_t b0 = Ks[(nf * 8 + g) * KS_STRIDE + ks * 8 + tig];
                uint32_t b1 = Ks[(nf * 8 + g) * KS_STRIDE + ks * 8 + tig + 4];
                mma_tf32(sacc[nf], qa[ks], b0, b1);
            }
        }

        // ---- online softmax (rows r_lo via c0/c1, r_lo+8 via c2/c3)
        float rm0 = -1e30f, rm1 = -1e30f;
#pragma unroll
        for (int nf = 0; nf < 8; nf++) {
            rm0 = fmaxf(rm0, fmaxf(sacc[nf][0], sacc[nf][1]));
            rm1 = fmaxf(rm1, fmaxf(sacc[nf][2], sacc[nf][3]));
        }
        rm0 = fmaxf(rm0, __shfl_xor_sync(0xffffffffu, rm0, 1));
        rm0 = fmaxf(rm0, __shfl_xor_sync(0xffffffffu, rm0, 2));
        rm1 = fmaxf(rm1, __shfl_xor_sync(0xffffffffu, rm1, 1));
        rm1 = fmaxf(rm1, __shfl_xor_sync(0xffffffffu, rm1, 2));

        float mn0 = fmaxf(m0, rm0);
        float mn1 = fmaxf(m1, rm1);
        float al0 = __expf(m0 - mn0);
        float al1 = __expf(m1 - mn1);
        float rs0 = 0.0f, rs1 = 0.0f;
#pragma unroll
        for (int nf = 0; nf < 8; nf++) {
            float p0 = __expf(sacc[nf][0] - mn0);
            float p1 = __expf(sacc[nf][1] - mn0);
            float p2 = __expf(sacc[nf][2] - mn1);
            float p3 = __expf(sacc[nf][3] - mn1);
            rs0 += p0 + p1;
            rs1 += p2 + p3;
            Ps[r_lo * PS_STRIDE + nf * 8 + 2 * tig]     = f2tf32(p0);
            Ps[r_lo * PS_STRIDE + nf * 8 + 2 * tig + 1] = f2tf32(p1);
            Ps[(r_lo + 8) * PS_STRIDE + nf * 8 + 2 * tig]     = f2tf32(p2);
            Ps[(r_lo + 8) * PS_STRIDE + nf * 8 + 2 * tig + 1] = f2tf32(p3);
        }
        rs0 += __shfl_xor_sync(0xffffffffu, rs0, 1);
        rs0 += __shfl_xor_sync(0xffffffffu, rs0, 2);
        rs1 += __shfl_xor_sync(0xffffffffu, rs1, 1);
        rs1 += __shfl_xor_sync(0xffffffffu, rs1, 2);
        l0 = al0 * l0 + rs0;
        l1 = al1 * l1 + rs1;
        m0 = mn0;
        m1 = mn1;
#pragma unroll
        for (int nf = 0; nf < 16; nf++) {
            oacc[nf][0] *= al0;
            oacc[nf][1] *= al0;
            oacc[nf][2] *= al1;
            oacc[nf][3] *= al1;
        }
        __syncwarp();   // Ps visibility within warp

        // ---- O += P @ V (16x128 per warp)
#pragma unroll
        for (int ks = 0; ks < 8; ks++) {
            uint32_t pa[4];
            pa[0] = Ps[r_lo * PS_STRIDE + ks * 8 + tig];
            pa[1] = Ps[(r_lo + 8) * PS_STRIDE + ks * 8 + tig];
            pa[2] = Ps[r_lo * PS_STRIDE + ks * 8 + tig + 4];
            pa[3] = Ps[(r_lo + 8) * PS_STRIDE + ks * 8 + tig + 4];
#pragma unroll
            for (int nf = 0; nf < 16; nf++) {
                uint32_t b0 = Vs[(ks * 8 + tig) * VS_STRIDE + nf * 8 + g];
                uint32_t b1 = Vs[(ks * 8 + tig + 4) * VS_STRIDE + nf * 8 + g];
                mma_tf32(oacc[nf], pa, b0, b1);
            }
        }
    }

    // ---- normalize + write z
    float inv0 = 1.0f / l0;
    float inv1 = 1.0f / l1;
    const size_t row0 = (size_t)(b * SEQ + n0 + r_lo);
    const size_t row1 = row0 + 8;
#pragma unroll
    for (int nf = 0; nf < 16; nf++) {
        int col = h * HDIM + nf * 8 + 2 * tig;
        float2 lo = make_float2(oacc[nf][0] * inv0, oacc[nf][1] * inv0);
        float2 hi = make_float2(oacc[nf][2] * inv1, oacc[nf][3] * inv1);
        *reinterpret_cast<float2*>(z + row0 * INNER + col) = lo;
        *reinterpret_cast<float2*>(z + row1 * INNER + col) = hi;
    }
}

// ---------------------------------------------------------------------------
// Launch
// ---------------------------------------------------------------------------
extern "C" void kernel_launch(void* const* d_in, const int* in_sizes, int n_in,
                              void* d_out, int out_size)
{
    const float* x     = (const float*)d_in[0];   // [8,1024,128]
    const float* w_qkv = (const float*)d_in[1];   // [128,3072]
    const float* w_out = (const float*)d_in[2];   // [1024,128]
    const float* b_out = (const float*)d_in[3];   // [128]
    float* out = (float*)d_out;                   // [8,1024,128]

    void* qkvp = nullptr;
    void* zp   = nullptr;
    cudaGetSymbolAddress(&qkvp, g_qkv);
    cudaGetSymbolAddress(&zp, g_z);
    float* qkv = (float*)qkvp;
    float* zb  = (float*)zp;

    // 1) QKV projection: [8192,128] @ [128,3072] (fp32)
    {
        dim3 grid(QKVC / 128, NTOK / 128);
        sgemm_kernel<128, 128, 32, 8, 8><<<grid, 256>>>(
            x, w_qkv, qkv, nullptr, NTOK, QKVC, DMODEL);
    }

    // 2) attention (tf32 tensor cores)
    {
        cudaFuncSetAttribute(attn_tc_kernel,
                             cudaFuncAttributeMaxDynamicSharedMemorySize,
                             ATT_SMEM_BYTES);
        dim3 grid(SEQ / 64, NHEADS, BATCH);
        attn_tc_kernel<<<grid, 128, ATT_SMEM_BYTES>>>(qkv, zb);
    }

    // 3) output projection: [8192,1024] @ [1024,128] + bias (fp32)
    {
        dim3 grid(DMODEL / 64, NTOK / 64);
        sgemm_kernel<64, 64, 64, 4, 4><<<grid, 256>>>(
            zb, w_out, out, b_out, NTOK, DMODEL, INNER);
    }
}

// round 5
// speedup vs baseline: 2.7547x; 1.2204x over previous
#include <cuda_runtime.h>
#include <math.h>
#include <stdint.h>

// Problem constants
#define NTOK   8192      // B*N = 8*1024
#define DMODEL 128
#define NHEADS 8
#define HDIM   128
#define INNER  1024      // NHEADS*HDIM
#define QKVC   3072      // 3*INNER
#define SEQ    1024
#define BATCH  8

// Scratch buffers (no allocation allowed -> device globals)
__device__ float g_qkv[(size_t)NTOK * QKVC];   // 96 MB
__device__ float g_z[(size_t)NTOK * INNER];    // 32 MB

// ---------------------------------------------------------------------------
// tf32 mma.sync helpers
// ---------------------------------------------------------------------------
__device__ __forceinline__ uint32_t f2tf32(float x) {
    uint32_t u;
    asm("cvt.rna.tf32.f32 %0, %1;" : "=r"(u) : "f"(x));
    return u;
}

__device__ __forceinline__ void mma_tf32(float* c, const uint32_t* a,
                                         uint32_t b0, uint32_t b1) {
    asm volatile(
        "mma.sync.aligned.m16n8k8.row.col.f32.tf32.tf32.f32 "
        "{%0,%1,%2,%3},{%4,%5,%6,%7},{%8,%9},{%0,%1,%2,%3};"
        : "+f"(c[0]), "+f"(c[1]), "+f"(c[2]), "+f"(c[3])
        : "r"(a[0]), "r"(a[1]), "r"(a[2]), "r"(a[3]), "r"(b0), "r"(b1));
}

// ---------------------------------------------------------------------------
// tf32 tensor-core GEMM: C[M,N] = A[M,K] @ B[K,N] (+bias), row-major.
// Fragment layouts (m16n8k8.row.col), thread (g=lane>>2, t=lane&3):
//   a0=A[g][t]  a1=A[g+8][t]  a2=A[g][t+4]  a3=A[g+8][t+4]
//   b0=B[t][g]  b1=B[t+4][g]
//   c0=C[g][2t] c1=C[g][2t+1] c2=C[g+8][2t] c3=C[g+8][2t+1]
// Smem strides: As stride BK+4=36 (4g+t bijective mod 32 -> conflict-free),
//               Bs stride BN+8 (==8 mod 32: 8t+g bijective -> conflict-free).
// ---------------------------------------------------------------------------
template<int BM, int BN, int BK, int WM, int WN, bool BIAS>
__global__ __launch_bounds__((BM/WM)*(BN/WN)*32)
void tf32_gemm_kernel(const float* __restrict__ A,
                      const float* __restrict__ B,
                      float* __restrict__ C,
                      const float* __restrict__ bias,
                      int M, int N, int K)
{
    constexpr int WARPS_M = BM / WM;
    constexpr int WARPS_N = BN / WN;
    constexpr int NT = WARPS_M * WARPS_N * 32;
    constexpr int MF = WM / 16;
    constexpr int NF = WN / 8;
    constexpr int AS_STRIDE = BK + 4;
    constexpr int BS_STRIDE = BN + 8;

    __shared__ uint32_t As[BM * AS_STRIDE];
    __shared__ uint32_t Bs[BK * BS_STRIDE];

    const int tid  = threadIdx.x;
    const int w    = tid >> 5;
    const int lane = tid & 31;
    const int g    = lane >> 2;
    const int tig  = lane & 3;
    const int wm0  = (w / WARPS_N) * WM;
    const int wn0  = (w % WARPS_N) * WN;
    const int m0   = blockIdx.y * BM;
    const int n0   = blockIdx.x * BN;

    float acc[MF][NF][4];
#pragma unroll
    for (int i = 0; i < MF; i++)
#pragma unroll
        for (int j = 0; j < NF; j++)
#pragma unroll
            for (int c = 0; c < 4; c++) acc[i][j][c] = 0.0f;

    for (int k0 = 0; k0 < K; k0 += BK) {
        // stage A tile [BM][BK] as tf32
        constexpr int AF4 = BM * BK / 4;
#pragma unroll
        for (int f = 0; f < AF4 / NT; f++) {
            int idx = tid + f * NT;
            int row = idx / (BK / 4);
            int c4  = idx % (BK / 4);
            float4 v = *reinterpret_cast<const float4*>(
                A + (size_t)(m0 + row) * K + k0 + 4 * c4);
            uint4 u;
            u.x = f2tf32(v.x); u.y = f2tf32(v.y);
            u.z = f2tf32(v.z); u.w = f2tf32(v.w);
            *reinterpret_cast<uint4*>(&As[row * AS_STRIDE + 4 * c4]) = u;
        }
        // stage B tile [BK][BN] as tf32
        constexpr int BF4 = BK * BN / 4;
#pragma unroll
        for (int f = 0; f < BF4 / NT; f++) {
            int idx = tid + f * NT;
            int row = idx / (BN / 4);
            int c4  = idx % (BN / 4);
            float4 v = *reinterpret_cast<const float4*>(
                B + (size_t)(k0 + row) * N + n0 + 4 * c4);
            uint4 u;
            u.x = f2tf32(v.x); u.y = f2tf32(v.y);
            u.z = f2tf32(v.z); u.w = f2tf32(v.w);
            *reinterpret_cast<uint4*>(&Bs[row * BS_STRIDE + 4 * c4]) = u;
        }
        __syncthreads();

#pragma unroll
        for (int k8 = 0; k8 < BK / 8; k8++) {
            uint32_t afr[MF][4];
#pragma unroll
            for (int mf = 0; mf < MF; mf++) {
                const int r = wm0 + mf * 16 + g;
                afr[mf][0] = As[r * AS_STRIDE + k8 * 8 + tig];
                afr[mf][1] = As[(r + 8) * AS_STRIDE + k8 * 8 + tig];
                afr[mf][2] = As[r * AS_STRIDE + k8 * 8 + tig + 4];
                afr[mf][3] = As[(r + 8) * AS_STRIDE + k8 * 8 + tig + 4];
            }
#pragma unroll
            for (int nf = 0; nf < NF; nf++) {
                uint32_t b0 = Bs[(k8 * 8 + tig) * BS_STRIDE + wn0 + nf * 8 + g];
                uint32_t b1 = Bs[(k8 * 8 + tig + 4) * BS_STRIDE + wn0 + nf * 8 + g];
#pragma unroll
                for (int mf = 0; mf < MF; mf++)
                    mma_tf32(acc[mf][nf], afr[mf], b0, b1);
            }
        }
        __syncthreads();
    }

    // epilogue
#pragma unroll
    for (int mf = 0; mf < MF; mf++) {
        const size_t row_lo = (size_t)(m0 + wm0 + mf * 16 + g);
        const size_t row_hi = row_lo + 8;
#pragma unroll
        for (int nf = 0; nf < NF; nf++) {
            const int col = n0 + wn0 + nf * 8 + 2 * tig;
            float2 lo = make_float2(acc[mf][nf][0], acc[mf][nf][1]);
            float2 hi = make_float2(acc[mf][nf][2], acc[mf][nf][3]);
            if (BIAS) {
                lo.x += bias[col]; lo.y += bias[col + 1];
                hi.x += bias[col]; hi.y += bias[col + 1];
            }
            *reinterpret_cast<float2*>(C + row_lo * N + col) = lo;
            *reinterpret_cast<float2*>(C + row_hi * N + col) = hi;
        }
    }
}

// ---------------------------------------------------------------------------
// Flash attention on tensor cores (tf32, fp32 accumulate). (unchanged)
// Block: 128 threads (4 warps), 64 query rows of one (b, h). KV tile = 64.
// ---------------------------------------------------------------------------
#define KS_STRIDE 132
#define VS_STRIDE 136
#define PS_STRIDE 68
#define ATT_SMEM_U32 (64 * KS_STRIDE + 64 * VS_STRIDE + 64 * PS_STRIDE)
#define ATT_SMEM_BYTES (ATT_SMEM_U32 * 4)

__global__ __launch_bounds__(128)
void attn_tc_kernel(const float* __restrict__ qkv, float* __restrict__ z)
{
    extern __shared__ uint32_t sm[];
    uint32_t* Ks = sm;                              // [64][132]
    uint32_t* Vs = sm + 64 * KS_STRIDE;             // [64][136]
    uint32_t* Ps = Vs + 64 * VS_STRIDE;             // [64][68]

    const int tid  = threadIdx.x;
    const int w    = tid >> 5;
    const int lane = tid & 31;
    const int g    = lane >> 2;   // 0..7
    const int tig  = lane & 3;    // 0..3

    const int qt = blockIdx.x;
    const int h  = blockIdx.y;
    const int b  = blockIdx.z;
    const int n0 = qt * 64;

    const float scale = 0.08838834764831845f;   // 1/sqrt(128)

    const float* qbase = qkv + (size_t)(b * SEQ + n0) * QKVC + h * HDIM;
    const float* kbase = qkv + (size_t)(b * SEQ) * QKVC + INNER + h * HDIM;
    const float* vbase = kbase + INNER;

    // ---- stage Q (scaled, tf32) via Vs, then pull A-fragments to registers
    for (int f = tid; f < 2048; f += 128) {
        int row = f >> 5;
        int c4  = f & 31;
        float4 v = *reinterpret_cast<const float4*>(qbase + (size_t)row * QKVC + 4 * c4);
        uint4 u;
        u.x = f2tf32(v.x * scale);
        u.y = f2tf32(v.y * scale);
        u.z = f2tf32(v.z * scale);
        u.w = f2tf32(v.w * scale);
        *reinterpret_cast<uint4*>(Vs + row * VS_STRIDE + 4 * c4) = u;
    }
    __syncthreads();

    const int r_lo = w * 16 + g;     // block-local q row (low half)
    uint32_t qa[16][4];
#pragma unroll
    for (int ks = 0; ks < 16; ks++) {
        qa[ks][0] = Vs[r_lo * VS_STRIDE + ks * 8 + tig];
        qa[ks][1] = Vs[(r_lo + 8) * VS_STRIDE + ks * 8 + tig];
        qa[ks][2] = Vs[r_lo * VS_STRIDE + ks * 8 + tig + 4];
        qa[ks][3] = Vs[(r_lo + 8) * VS_STRIDE + ks * 8 + tig + 4];
    }

    float oacc[16][4];
#pragma unroll
    for (int nf = 0; nf < 16; nf++)
#pragma unroll
        for (int c = 0; c < 4; c++) oacc[nf][c] = 0.0f;
    float m0 = -1e30f, m1 = -1e30f, l0 = 0.0f, l1 = 0.0f;

    for (int j0 = 0; j0 < SEQ; j0 += 64) {
        __syncthreads();   // previous iteration finished reading Ks/Vs
        for (int f = tid; f < 2048; f += 128) {
            int row = f >> 5;
            int c4  = f & 31;
            float4 kv = *reinterpret_cast<const float4*>(
                kbase + (size_t)(j0 + row) * QKVC + 4 * c4);
            uint4 ku;
            ku.x = f2tf32(kv.x); ku.y = f2tf32(kv.y);
            ku.z = f2tf32(kv.z); ku.w = f2tf32(kv.w);
            *reinterpret_cast<uint4*>(Ks + row * KS_STRIDE + 4 * c4) = ku;
            float4 vv = *reinterpret_cast<const float4*>(
                vbase + (size_t)(j0 + row) * QKVC + 4 * c4);
            uint4 vu;
            vu.x = f2tf32(vv.x); vu.y = f2tf32(vv.y);
            vu.z = f2tf32(vv.z); vu.w = f2tf32(vv.w);
            *reinterpret_cast<uint4*>(Vs + row * VS_STRIDE + 4 * c4) = vu;
        }
        __syncthreads();

        // ---- S = Q @ K^T (64x64 per block, 16x64 per warp)
        float sacc[8][4];
#pragma unroll
        for (int nf = 0; nf < 8; nf++)
#pragma unroll
            for (int c = 0; c < 4; c++) sacc[nf][c] = 0.0f;

#pragma unroll
        for (int ks = 0; ks < 16; ks++) {
#pragma unroll
            for (int nf = 0; nf < 8; nf++) {
                uint32_t b0 = Ks[(nf * 8 + g) * KS_STRIDE + ks * 8 + tig];
                uint32_t b1 = Ks[(nf * 8 + g) * KS_STRIDE + ks * 8 + tig + 4];
                mma_tf32(sacc[nf], qa[ks], b0, b1);
            }
        }

        // ---- online softmax (rows r_lo via c0/c1, r_lo+8 via c2/c3)
        float rm0 = -1e30f, rm1 = -1e30f;
#pragma unroll
        for (int nf = 0; nf < 8; nf++) {
            rm0 = fmaxf(rm0, fmaxf(sacc[nf][0], sacc[nf][1]));
            rm1 = fmaxf(rm1, fmaxf(sacc[nf][2], sacc[nf][3]));
        }
        rm0 = fmaxf(rm0, __shfl_xor_sync(0xffffffffu, rm0, 1));
        rm0 = fmaxf(rm0, __shfl_xor_sync(0xffffffffu, rm0, 2));
        rm1 = fmaxf(rm1, __shfl_xor_sync(0xffffffffu, rm1, 1));
        rm1 = fmaxf(rm1, __shfl_xor_sync(0xffffffffu, rm1, 2));

        float mn0 = fmaxf(m0, rm0);
        float mn1 = fmaxf(m1, rm1);
        float al0 = __expf(m0 - mn0);
        float al1 = __expf(m1 - mn1);
        float rs0 = 0.0f, rs1 = 0.0f;
#pragma unroll
        for (int nf = 0; nf < 8; nf++) {
            float p0 = __expf(sacc[nf][0] - mn0);
            float p1 = __expf(sacc[nf][1] - mn0);
            float p2 = __expf(sacc[nf][2] - mn1);
            float p3 = __expf(sacc[nf][3] - mn1);
            rs0 += p0 + p1;
            rs1 += p2 + p3;
            Ps[r_lo * PS_STRIDE + nf * 8 + 2 * tig]     = f2tf32(p0);
            Ps[r_lo * PS_STRIDE + nf * 8 + 2 * tig + 1] = f2tf32(p1);
            Ps[(r_lo + 8) * PS_STRIDE + nf * 8 + 2 * tig]     = f2tf32(p2);
            Ps[(r_lo + 8) * PS_STRIDE + nf * 8 + 2 * tig + 1] = f2tf32(p3);
        }
        rs0 += __shfl_xor_sync(0xffffffffu, rs0, 1);
        rs0 += __shfl_xor_sync(0xffffffffu, rs0, 2);
        rs1 += __shfl_xor_sync(0xffffffffu, rs1, 1);
        rs1 += __shfl_xor_sync(0xffffffffu, rs1, 2);
        l0 = al0 * l0 + rs0;
        l1 = al1 * l1 + rs1;
        m0 = mn0;
        m1 = mn1;
#pragma unroll
        for (int nf = 0; nf < 16; nf++) {
            oacc[nf][0] *= al0;
            oacc[nf][1] *= al0;
            oacc[nf][2] *= al1;
            oacc[nf][3] *= al1;
        }
        __syncwarp();   // Ps visibility within warp

        // ---- O += P @ V (16x128 per warp)
#pragma unroll
        for (int ks = 0; ks < 8; ks++) {
            uint32_t pa[4];
            pa[0] = Ps[r_lo * PS_STRIDE + ks * 8 + tig];
            pa[1] = Ps[(r_lo + 8) * PS_STRIDE + ks * 8 + tig];
            pa[2] = Ps[r_lo * PS_STRIDE + ks * 8 + tig + 4];
            pa[3] = Ps[(r_lo + 8) * PS_STRIDE + ks * 8 + tig + 4];
#pragma unroll
            for (int nf = 0; nf < 16; nf++) {
                uint32_t b0 = Vs[(ks * 8 + tig) * VS_STRIDE + nf * 8 + g];
                uint32_t b1 = Vs[(ks * 8 + tig + 4) * VS_STRIDE + nf * 8 + g];
                mma_tf32(oacc[nf], pa, b0, b1);
            }
        }
    }

    // ---- normalize + write z
    float inv0 = 1.0f / l0;
    float inv1 = 1.0f / l1;
    const size_t row0 = (size_t)(b * SEQ + n0 + r_lo);
    const size_t row1 = row0 + 8;
#pragma unroll
    for (int nf = 0; nf < 16; nf++) {
        int col = h * HDIM + nf * 8 + 2 * tig;
        float2 lo = make_float2(oacc[nf][0] * inv0, oacc[nf][1] * inv0);
        float2 hi = make_float2(oacc[nf][2] * inv1, oacc[nf][3] * inv1);
        *reinterpret_cast<float2*>(z + row0 * INNER + col) = lo;
        *reinterpret_cast<float2*>(z + row1 * INNER + col) = hi;
    }
}

// ---------------------------------------------------------------------------
// Launch
// ---------------------------------------------------------------------------
extern "C" void kernel_launch(void* const* d_in, const int* in_sizes, int n_in,
                              void* d_out, int out_size)
{
    const float* x     = (const float*)d_in[0];   // [8,1024,128]
    const float* w_qkv = (const float*)d_in[1];   // [128,3072]
    const float* w_out = (const float*)d_in[2];   // [1024,128]
    const float* b_out = (const float*)d_in[3];   // [128]
    float* out = (float*)d_out;                   // [8,1024,128]

    void* qkvp = nullptr;
    void* zp   = nullptr;
    cudaGetSymbolAddress(&qkvp, g_qkv);
    cudaGetSymbolAddress(&zp, g_z);
    float* qkv = (float*)qkvp;
    float* zb  = (float*)zp;

    // 1) QKV projection: [8192,128] @ [128,3072] (tf32 tensor cores)
    {
        dim3 grid(QKVC / 128, NTOK / 128);
        tf32_gemm_kernel<128, 128, 32, 64, 64, false><<<grid, 128>>>(
            x, w_qkv, qkv, nullptr, NTOK, QKVC, DMODEL);
    }

    // 2) attention (tf32 tensor cores)
    {
        cudaFuncSetAttribute(attn_tc_kernel,
                             cudaFuncAttributeMaxDynamicSharedMemorySize,
                             ATT_SMEM_BYTES);
        dim3 grid(SEQ / 64, NHEADS, BATCH);
        attn_tc_kernel<<<grid, 128, ATT_SMEM_BYTES>>>(qkv, zb);
    }

    // 3) output projection: [8192,1024] @ [1024,128] + bias (tf32 tensor cores)
    {
        dim3 grid(DMODEL / 128, NTOK / 64);
        tf32_gemm_kernel<64, 128, 32, 32, 64, true><<<grid, 128>>>(
            zb, w_out, out, b_out, NTOK, DMODEL, INNER);
    }
}

// round 8
// speedup vs baseline: 2.7849x; 1.0110x over previous
#include <cuda_runtime.h>
#include <math.h>
#include <stdint.h>

// Problem constants
#define NTOK   8192      // B*N = 8*1024
#define DMODEL 128
#define NHEADS 8
#define HDIM   128
#define INNER  1024      // NHEADS*HDIM
#define QKVC   3072      // 3*INNER
#define SEQ    1024
#define BATCH  8

// Scratch buffers (no allocation allowed -> device globals)
__device__ float g_qkv[(size_t)NTOK * QKVC];   // 96 MB
__device__ float g_z[(size_t)NTOK * INNER];    // 32 MB

// ---------------------------------------------------------------------------
// tf32 mma.sync helpers
// ---------------------------------------------------------------------------
__device__ __forceinline__ uint32_t f2tf32(float x) {
    uint32_t u;
    asm("cvt.rna.tf32.f32 %0, %1;" : "=r"(u) : "f"(x));
    return u;
}

__device__ __forceinline__ void mma_tf32(float* c, const uint32_t* a,
                                         uint32_t b0, uint32_t b1) {
    asm volatile(
        "mma.sync.aligned.m16n8k8.row.col.f32.tf32.tf32.f32 "
        "{%0,%1,%2,%3},{%4,%5,%6,%7},{%8,%9},{%0,%1,%2,%3};"
        : "+f"(c[0]), "+f"(c[1]), "+f"(c[2]), "+f"(c[3])
        : "r"(a[0]), "r"(a[1]), "r"(a[2]), "r"(a[3]), "r"(b0), "r"(b1));
}

// ---------------------------------------------------------------------------
// tf32 tensor-core GEMM: C[M,N] = A[M,K] @ B[K,N] (+bias), row-major.
// ---------------------------------------------------------------------------
template<int BM, int BN, int BK, int WM, int WN, bool BIAS>
__global__ __launch_bounds__((BM/WM)*(BN/WN)*32)
void tf32_gemm_kernel(const float* __restrict__ A,
                      const float* __restrict__ B,
                      float* __restrict__ C,
                      const float* __restrict__ bias,
                      int M, int N, int K)
{
    constexpr int WARPS_M = BM / WM;
    constexpr int WARPS_N = BN / WN;
    constexpr int NT = WARPS_M * WARPS_N * 32;
    constexpr int MF = WM / 16;
    constexpr int NF = WN / 8;
    constexpr int AS_STRIDE = BK + 4;
    constexpr int BS_STRIDE = BN + 8;

    __shared__ uint32_t As[BM * AS_STRIDE];
    __shared__ uint32_t Bs[BK * BS_STRIDE];

    const int tid  = threadIdx.x;
    const int w    = tid >> 5;
    const int lane = tid & 31;
    const int g    = lane >> 2;
    const int tig  = lane & 3;
    const int wm0  = (w / WARPS_N) * WM;
    const int wn0  = (w % WARPS_N) * WN;
    const int m0   = blockIdx.y * BM;
    const int n0   = blockIdx.x * BN;

    float acc[MF][NF][4];
#pragma unroll
    for (int i = 0; i < MF; i++)
#pragma unroll
        for (int j = 0; j < NF; j++)
#pragma unroll
            for (int c = 0; c < 4; c++) acc[i][j][c] = 0.0f;

    for (int k0 = 0; k0 < K; k0 += BK) {
        constexpr int AF4 = BM * BK / 4;
#pragma unroll
        for (int f = 0; f < AF4 / NT; f++) {
            int idx = tid + f * NT;
            int row = idx / (BK / 4);
            int c4  = idx % (BK / 4);
            float4 v = *reinterpret_cast<const float4*>(
                A + (size_t)(m0 + row) * K + k0 + 4 * c4);
            uint4 u;
            u.x = f2tf32(v.x); u.y = f2tf32(v.y);
            u.z = f2tf32(v.z); u.w = f2tf32(v.w);
            *reinterpret_cast<uint4*>(&As[row * AS_STRIDE + 4 * c4]) = u;
        }
        constexpr int BF4 = BK * BN / 4;
#pragma unroll
        for (int f = 0; f < BF4 / NT; f++) {
            int idx = tid + f * NT;
            int row = idx / (BN / 4);
            int c4  = idx % (BN / 4);
            float4 v = *reinterpret_cast<const float4*>(
                B + (size_t)(k0 + row) * N + n0 + 4 * c4);
            uint4 u;
            u.x = f2tf32(v.x); u.y = f2tf32(v.y);
            u.z = f2tf32(v.z); u.w = f2tf32(v.w);
            *reinterpret_cast<uint4*>(&Bs[row * BS_STRIDE + 4 * c4]) = u;
        }
        __syncthreads();

#pragma unroll
        for (int k8 = 0; k8 < BK / 8; k8++) {
            uint32_t afr[MF][4];
#pragma unroll
            for (int mf = 0; mf < MF; mf++) {
                const int r = wm0 + mf * 16 + g;
                afr[mf][0] = As[r * AS_STRIDE + k8 * 8 + tig];
                afr[mf][1] = As[(r + 8) * AS_STRIDE + k8 * 8 + tig];
                afr[mf][2] = As[r * AS_STRIDE + k8 * 8 + tig + 4];
                afr[mf][3] = As[(r + 8) * AS_STRIDE + k8 * 8 + tig + 4];
            }
#pragma unroll
            for (int nf = 0; nf < NF; nf++) {
                uint32_t b0 = Bs[(k8 * 8 + tig) * BS_STRIDE + wn0 + nf * 8 + g];
                uint32_t b1 = Bs[(k8 * 8 + tig + 4) * BS_STRIDE + wn0 + nf * 8 + g];
#pragma unroll
                for (int mf = 0; mf < MF; mf++)
                    mma_tf32(acc[mf][nf], afr[mf], b0, b1);
            }
        }
        __syncthreads();
    }

#pragma unroll
    for (int mf = 0; mf < MF; mf++) {
        const size_t row_lo = (size_t)(m0 + wm0 + mf * 16 + g);
        const size_t row_hi = row_lo + 8;
#pragma unroll
        for (int nf = 0; nf < NF; nf++) {
            const int col = n0 + wn0 + nf * 8 + 2 * tig;
            float2 lo = make_float2(acc[mf][nf][0], acc[mf][nf][1]);
            float2 hi = make_float2(acc[mf][nf][2], acc[mf][nf][3]);
            if (BIAS) {
                lo.x += bias[col]; lo.y += bias[col + 1];
                hi.x += bias[col]; hi.y += bias[col + 1];
            }
            *reinterpret_cast<float2*>(C + row_lo * N + col) = lo;
            *reinterpret_cast<float2*>(C + row_hi * N + col) = hi;
        }
    }
}

// ---------------------------------------------------------------------------
// Flash attention on tensor cores (tf32, fp32 accumulate).
// Block: 128 threads (4 warps), 64 q-rows of one (b,h). KV tile = 64.
//
// Permuted smem layouts for vectorized fragment loads:
//  K/Q ("k-residue" layout): element (row, col) at  (col%4)*2312 + row*36 + col/4
//    -> thread (g,t) LDS.128 at t*2312 + row*36 + 4*G yields cols
//       {t,t+4,t+8,t+12}+16G = b0/b1 fragments for ks=2G and 2G+1.
//       Banks: 8t + 4g + {0..3}  -> conflict-free.
//  V ("n-residue" layout): element (row, col) at (col%8)*1296 + row*20 + col/8
//    -> thread (g,t) LDS.128 at g*1296 + row*20 + 4*Gv yields cols
//       {g+32Gv, g+8+32Gv, ...} = b0 (or b1) for nf=4Gv..4Gv+3.
//       Banks: 16g + 20t + {0..3} -> conflict-free.
// ---------------------------------------------------------------------------
#define KM_BLK  2312     // 64*36 + 8  (== 8 mod 32)
#define K_RS    36
#define VM_BLK  1296     // 64*20 + 16 (== 16 mod 32)
#define V_RS    20
#define PS_STRIDE 68
#define ATT_KS_U32 (4 * KM_BLK)
#define ATT_VS_U32 (8 * VM_BLK)
#define ATT_PS_U32 (64 * PS_STRIDE)
#define ATT_SMEM_U32 (ATT_KS_U32 + ATT_VS_U32 + ATT_PS_U32)
#define ATT_SMEM_BYTES (ATT_SMEM_U32 * 4)

__global__ __launch_bounds__(128)
void attn_tc_kernel(const float* __restrict__ qkv, float* __restrict__ z)
{
    extern __shared__ uint32_t sm[];
    uint32_t* Ks = sm;                       // K (and initially Q), k-residue layout
    uint32_t* Vs = sm + ATT_KS_U32;          // V, n-residue layout
    uint32_t* Ps = Vs + ATT_VS_U32;          // P, row-major stride 68

    const int tid  = threadIdx.x;
    const int w    = tid >> 5;
    const int lane = tid & 31;
    const int g    = lane >> 2;   // 0..7
    const int tig  = lane & 3;    // 0..3

    const int qt = blockIdx.x;
    const int h  = blockIdx.y;
    const int b  = blockIdx.z;
    const int n0 = qt * 64;

    const float scale = 0.08838834764831845f;   // 1/sqrt(128)

    const float* qbase = qkv + (size_t)(b * SEQ + n0) * QKVC + h * HDIM;
    const float* kbase = qkv + (size_t)(b * SEQ) * QKVC + INNER + h * HDIM;
    const float* vbase = kbase + INNER;

    // ---- stage Q (scaled, tf32) into Ks (k-residue layout)
    for (int f = tid; f < 2048; f += 128) {
        int row = f >> 5;
        int c4  = f & 31;
        float4 v = *reinterpret_cast<const float4*>(qbase + (size_t)row * QKVC + 4 * c4);
        int base = row * K_RS + c4;
        Ks[0 * KM_BLK + base] = f2tf32(v.x * scale);
        Ks[1 * KM_BLK + base] = f2tf32(v.y * scale);
        Ks[2 * KM_BLK + base] = f2tf32(v.z * scale);
        Ks[3 * KM_BLK + base] = f2tf32(v.w * scale);
    }
    __syncthreads();

    const int r_lo = w * 16 + g;     // block-local q row (low half)
    uint32_t qa[16][4];
#pragma unroll
    for (int G = 0; G < 8; G++) {
        uint4 alo = *reinterpret_cast<const uint4*>(&Ks[tig * KM_BLK + r_lo * K_RS + 4 * G]);
        uint4 ahi = *reinterpret_cast<const uint4*>(&Ks[tig * KM_BLK + (r_lo + 8) * K_RS + 4 * G]);
        qa[2 * G][0]     = alo.x; qa[2 * G][1]     = ahi.x;
        qa[2 * G][2]     = alo.y; qa[2 * G][3]     = ahi.y;
        qa[2 * G + 1][0] = alo.z; qa[2 * G + 1][1] = ahi.z;
        qa[2 * G + 1][2] = alo.w; qa[2 * G + 1][3] = ahi.w;
    }

    float oacc[16][4];
#pragma unroll
    for (int nf = 0; nf < 16; nf++)
#pragma unroll
        for (int c = 0; c < 4; c++) oacc[nf][c] = 0.0f;
    float m0 = -1e30f, m1 = -1e30f, l0 = 0.0f, l1 = 0.0f;

    for (int j0 = 0; j0 < SEQ; j0 += 64) {
        __syncthreads();   // previous iteration finished reading Ks/Vs (and qa read)
        // ---- stage K (k-residue) and V (n-residue) tiles as tf32
        for (int f = tid; f < 2048; f += 128) {
            int row = f >> 5;
            int c4  = f & 31;
            float4 kv = *reinterpret_cast<const float4*>(
                kbase + (size_t)(j0 + row) * QKVC + 4 * c4);
            int kb = row * K_RS + c4;
            Ks[0 * KM_BLK + kb] = f2tf32(kv.x);
            Ks[1 * KM_BLK + kb] = f2tf32(kv.y);
            Ks[2 * KM_BLK + kb] = f2tf32(kv.z);
            Ks[3 * KM_BLK + kb] = f2tf32(kv.w);
            float4 vv = *reinterpret_cast<const float4*>(
                vbase + (size_t)(j0 + row) * QKVC + 4 * c4);
            // col = 4*c4 + i -> m8 = ((c4&1)<<2)+i, j = c4>>1
            int vb = row * V_RS + (c4 >> 1);
            int m8b = (c4 & 1) << 2;
            Vs[(m8b + 0) * VM_BLK + vb] = f2tf32(vv.x);
            Vs[(m8b + 1) * VM_BLK + vb] = f2tf32(vv.y);
            Vs[(m8b + 2) * VM_BLK + vb] = f2tf32(vv.z);
            Vs[(m8b + 3) * VM_BLK + vb] = f2tf32(vv.w);
        }
        __syncthreads();

        // ---- S = Q @ K^T (16x64 per warp)
        float sacc[8][4];
#pragma unroll
        for (int nf = 0; nf < 8; nf++)
#pragma unroll
            for (int c = 0; c < 4; c++) sacc[nf][c] = 0.0f;

#pragma unroll
        for (int G = 0; G < 8; G++) {
#pragma unroll
            for (int nf = 0; nf < 8; nf++) {
                uint4 kb = *reinterpret_cast<const uint4*>(
                    &Ks[tig * KM_BLK + (nf * 8 + g) * K_RS + 4 * G]);
                mma_tf32(sacc[nf], qa[2 * G], kb.x, kb.y);
                mma_tf32(sacc[nf], qa[2 * G + 1], kb.z, kb.w);
            }
        }

        // ---- online softmax (rows r_lo via c0/c1, r_lo+8 via c2/c3)
        float rm0 = -1e30f, rm1 = -1e30f;
#pragma unroll
        for (int nf = 0; nf < 8; nf++) {
            rm0 = fmaxf(rm0, fmaxf(sacc[nf][0], sacc[nf][1]));
            rm1 = fmaxf(rm1, fmaxf(sacc[nf][2], sacc[nf][3]));
        }
        rm0 = fmaxf(rm0, __shfl_xor_sync(0xffffffffu, rm0, 1));
        rm0 = fmaxf(rm0, __shfl_xor_sync(0xffffffffu, rm0, 2));
        rm1 = fmaxf(rm1, __shfl_xor_sync(0xffffffffu, rm1, 1));
        rm1 = fmaxf(rm1, __shfl_xor_sync(0xffffffffu, rm1, 2));

        float mn0 = fmaxf(m0, rm0);
        float mn1 = fmaxf(m1, rm1);
        float al0 = __expf(m0 - mn0);
        float al1 = __expf(m1 - mn1);
        float rs0 = 0.0f, rs1 = 0.0f;
#pragma unroll
        for (int nf = 0; nf < 8; nf++) {
            float p0 = __expf(sacc[nf][0] - mn0);
            float p1 = __expf(sacc[nf][1] - mn0);
            float p2 = __expf(sacc[nf][2] - mn1);
            float p3 = __expf(sacc[nf][3] - mn1);
            rs0 += p0 + p1;
            rs1 += p2 + p3;
            Ps[r_lo * PS_STRIDE + nf * 8 + 2 * tig]     = f2tf32(p0);
            Ps[r_lo * PS_STRIDE + nf * 8 + 2 * tig + 1] = f2tf32(p1);
            Ps[(r_lo + 8) * PS_STRIDE + nf * 8 + 2 * tig]     = f2tf32(p2);
            Ps[(r_lo + 8) * PS_STRIDE + nf * 8 + 2 * tig + 1] = f2tf32(p3);
        }
        rs0 += __shfl_xor_sync(0xffffffffu, rs0, 1);
        rs0 += __shfl_xor_sync(0xffffffffu, rs0, 2);
        rs1 += __shfl_xor_sync(0xffffffffu, rs1, 1);
        rs1 += __shfl_xor_sync(0xffffffffu, rs1, 2);
        l0 = al0 * l0 + rs0;
        l1 = al1 * l1 + rs1;
        m0 = mn0;
        m1 = mn1;
#pragma unroll
        for (int nf = 0; nf < 16; nf++) {
            oacc[nf][0] *= al0;
            oacc[nf][1] *= al0;
            oacc[nf][2] *= al1;
            oacc[nf][3] *= al1;
        }
        __syncwarp();   // Ps visibility within warp

        // ---- O += P @ V (16x128 per warp)
#pragma unroll
        for (int ks = 0; ks < 8; ks++) {
            uint32_t pa[4];
            pa[0] = Ps[r_lo * PS_STRIDE + ks * 8 + tig];
            pa[1] = Ps[(r_lo + 8) * PS_STRIDE + ks * 8 + tig];
            pa[2] = Ps[r_lo * PS_STRIDE + ks * 8 + tig + 4];
            pa[3] = Ps[(r_lo + 8) * PS_STRIDE + ks * 8 + tig + 4];
#pragma unroll
            for (int Gv = 0; Gv < 4; Gv++) {
                uint4 v0 = *reinterpret_cast<const uint4*>(
                    &Vs[g * VM_BLK + (8 * ks + tig) * V_RS + 4 * Gv]);
                uint4 v1 = *reinterpret_cast<const uint4*>(
                    &Vs[g * VM_BLK + (8 * ks + tig + 4) * V_RS + 4 * Gv]);
                mma_tf32(oacc[4 * Gv + 0], pa, v0.x, v1.x);
                mma_tf32(oacc[4 * Gv + 1], pa, v0.y, v1.y);
                mma_tf32(oacc[4 * Gv + 2], pa, v0.z, v1.z);
                mma_tf32(oacc[4 * Gv + 3], pa, v0.w, v1.w);
            }
        }
    }

    // ---- normalize + write z
    float inv0 = 1.0f / l0;
    float inv1 = 1.0f / l1;
    const size_t row0 = (size_t)(b * SEQ + n0 + r_lo);
    const size_t row1 = row0 + 8;
#pragma unroll
    for (int nf = 0; nf < 16; nf++) {
        int col = h * HDIM + nf * 8 + 2 * tig;
        float2 lo = make_float2(oacc[nf][0] * inv0, oacc[nf][1] * inv0);
        float2 hi = make_float2(oacc[nf][2] * inv1, oacc[nf][3] * inv1);
        *reinterpret_cast<float2*>(z + row0 * INNER + col) = lo;
        *reinterpret_cast<float2*>(z + row1 * INNER + col) = hi;
    }
}

// ---------------------------------------------------------------------------
// Launch
// ---------------------------------------------------------------------------
extern "C" void kernel_launch(void* const* d_in, const int* in_sizes, int n_in,
                              void* d_out, int out_size)
{
    const float* x     = (const float*)d_in[0];   // [8,1024,128]
    const float* w_qkv = (const float*)d_in[1];   // [128,3072]
    const float* w_out = (const float*)d_in[2];   // [1024,128]
    const float* b_out = (const float*)d_in[3];   // [128]
    float* out = (float*)d_out;                   // [8,1024,128]

    void* qkvp = nullptr;
    void* zp   = nullptr;
    cudaGetSymbolAddress(&qkvp, g_qkv);
    cudaGetSymbolAddress(&zp, g_z);
    float* qkv = (float*)qkvp;
    float* zb  = (float*)zp;

    // 1) QKV projection: [8192,128] @ [128,3072] (tf32, 8 warps/block)
    {
        dim3 grid(QKVC / 128, NTOK / 128);
        tf32_gemm_kernel<128, 128, 32, 64, 32, false><<<grid, 256>>>(
            x, w_qkv, qkv, nullptr, NTOK, QKVC, DMODEL);
    }

    // 2) attention (tf32 tensor cores, permuted smem layouts)
    {
        cudaFuncSetAttribute(attn_tc_kernel,
                             cudaFuncAttributeMaxDynamicSharedMemorySize,
                             ATT_SMEM_BYTES);
        dim3 grid(SEQ / 64, NHEADS, BATCH);
        attn_tc_kernel<<<grid, 128, ATT_SMEM_BYTES>>>(qkv, zb);
    }

    // 3) output projection: [8192,1024] @ [1024,128] + bias (tf32)
    {
        dim3 grid(DMODEL / 128, NTOK / 32);
        tf32_gemm_kernel<32, 128, 64, 16, 64, true><<<grid, 128>>>(
            zb, w_out, out, b_out, NTOK, DMODEL, INNER);
    }
}

// round 10
// speedup vs baseline: 3.0724x; 1.1032x over previous
#include <cuda_runtime.h>
#include <math.h>
#include <stdint.h>

// Problem constants
#define NTOK   8192      // B*N = 8*1024
#define DMODEL 128
#define NHEADS 8
#define HDIM   128
#define INNER  1024      // NHEADS*HDIM
#define QKVC   3072      // 3*INNER
#define SEQ    1024
#define BATCH  8

// Scratch buffers (no allocation allowed -> device globals)
__device__ float g_qkv[(size_t)NTOK * QKVC];   // 96 MB
__device__ float g_z[(size_t)NTOK * INNER];    // 32 MB

// ---------------------------------------------------------------------------
// tf32 mma.sync helpers
// ---------------------------------------------------------------------------
__device__ __forceinline__ uint32_t f2tf32(float x) {
    uint32_t u;
    asm("cvt.rna.tf32.f32 %0, %1;" : "=r"(u) : "f"(x));
    return u;
}

__device__ __forceinline__ void mma_tf32(float* c, const uint32_t* a,
                                         uint32_t b0, uint32_t b1) {
    asm volatile(
        "mma.sync.aligned.m16n8k8.row.col.f32.tf32.tf32.f32 "
        "{%0,%1,%2,%3},{%4,%5,%6,%7},{%8,%9},{%0,%1,%2,%3};"
        : "+f"(c[0]), "+f"(c[1]), "+f"(c[2]), "+f"(c[3])
        : "r"(a[0]), "r"(a[1]), "r"(a[2]), "r"(a[3]), "r"(b0), "r"(b1));
}

// ---------------------------------------------------------------------------
// tf32 tensor-core GEMM: C[M,N] = A[M,K] @ B[K,N] (+bias), row-major.
// ---------------------------------------------------------------------------
template<int BM, int BN, int BK, int WM, int WN, bool BIAS>
__global__ __launch_bounds__((BM/WM)*(BN/WN)*32)
void tf32_gemm_kernel(const float* __restrict__ A,
                      const float* __restrict__ B,
                      float* __restrict__ C,
                      const float* __restrict__ bias,
                      int M, int N, int K)
{
    constexpr int WARPS_M = BM / WM;
    constexpr int WARPS_N = BN / WN;
    constexpr int NT = WARPS_M * WARPS_N * 32;
    constexpr int MF = WM / 16;
    constexpr int NF = WN / 8;
    constexpr int AS_STRIDE = BK + 4;
    constexpr int BS_STRIDE = BN + 8;

    __shared__ uint32_t As[BM * AS_STRIDE];
    __shared__ uint32_t Bs[BK * BS_STRIDE];

    const int tid  = threadIdx.x;
    const int w    = tid >> 5;
    const int lane = tid & 31;
    const int g    = lane >> 2;
    const int tig  = lane & 3;
    const int wm0  = (w / WARPS_N) * WM;
    const int wn0  = (w % WARPS_N) * WN;
    const int m0   = blockIdx.y * BM;
    const int n0   = blockIdx.x * BN;

    float acc[MF][NF][4];
#pragma unroll
    for (int i = 0; i < MF; i++)
#pragma unroll
        for (int j = 0; j < NF; j++)
#pragma unroll
            for (int c = 0; c < 4; c++) acc[i][j][c] = 0.0f;

    for (int k0 = 0; k0 < K; k0 += BK) {
        constexpr int AF4 = BM * BK / 4;
#pragma unroll
        for (int f = 0; f < AF4 / NT; f++) {
            int idx = tid + f * NT;
            int row = idx / (BK / 4);
            int c4  = idx % (BK / 4);
            float4 v = *reinterpret_cast<const float4*>(
                A + (size_t)(m0 + row) * K + k0 + 4 * c4);
            uint4 u;
            u.x = f2tf32(v.x); u.y = f2tf32(v.y);
            u.z = f2tf32(v.z); u.w = f2tf32(v.w);
            *reinterpret_cast<uint4*>(&As[row * AS_STRIDE + 4 * c4]) = u;
        }
        constexpr int BF4 = BK * BN / 4;
#pragma unroll
        for (int f = 0; f < BF4 / NT; f++) {
            int idx = tid + f * NT;
            int row = idx / (BN / 4);
            int c4  = idx % (BN / 4);
            float4 v = *reinterpret_cast<const float4*>(
                B + (size_t)(k0 + row) * N + n0 + 4 * c4);
            uint4 u;
            u.x = f2tf32(v.x); u.y = f2tf32(v.y);
            u.z = f2tf32(v.z); u.w = f2tf32(v.w);
            *reinterpret_cast<uint4*>(&Bs[row * BS_STRIDE + 4 * c4]) = u;
        }
        __syncthreads();

#pragma unroll
        for (int k8 = 0; k8 < BK / 8; k8++) {
            uint32_t afr[MF][4];
#pragma unroll
            for (int mf = 0; mf < MF; mf++) {
                const int r = wm0 + mf * 16 + g;
                afr[mf][0] = As[r * AS_STRIDE + k8 * 8 + tig];
                afr[mf][1] = As[(r + 8) * AS_STRIDE + k8 * 8 + tig];
                afr[mf][2] = As[r * AS_STRIDE + k8 * 8 + tig + 4];
                afr[mf][3] = As[(r + 8) * AS_STRIDE + k8 * 8 + tig + 4];
            }
#pragma unroll
            for (int nf = 0; nf < NF; nf++) {
                uint32_t b0 = Bs[(k8 * 8 + tig) * BS_STRIDE + wn0 + nf * 8 + g];
                uint32_t b1 = Bs[(k8 * 8 + tig + 4) * BS_STRIDE + wn0 + nf * 8 + g];
#pragma unroll
                for (int mf = 0; mf < MF; mf++)
                    mma_tf32(acc[mf][nf], afr[mf], b0, b1);
            }
        }
        __syncthreads();
    }

#pragma unroll
    for (int mf = 0; mf < MF; mf++) {
        const size_t row_lo = (size_t)(m0 + wm0 + mf * 16 + g);
        const size_t row_hi = row_lo + 8;
#pragma unroll
        for (int nf = 0; nf < NF; nf++) {
            const int col = n0 + wn0 + nf * 8 + 2 * tig;
            float2 lo = make_float2(acc[mf][nf][0], acc[mf][nf][1]);
            float2 hi = make_float2(acc[mf][nf][2], acc[mf][nf][3]);
            if (BIAS) {
                lo.x += bias[col]; lo.y += bias[col + 1];
                hi.x += bias[col]; hi.y += bias[col + 1];
            }
            *reinterpret_cast<float2*>(C + row_lo * N + col) = lo;
            *reinterpret_cast<float2*>(C + row_hi * N + col) = hi;
        }
    }
}

// ---------------------------------------------------------------------------
// Flash attention on tensor cores (tf32, fp32 accumulate).
// Block: 256 threads (8 warps), 128 q-rows of one (b,h). KV tile = 64.
// Register-prefetch double buffering: next tile's K/V LDGs are issued right
// after the staging barrier and consumed at the next iteration's STS, hiding
// global latency behind a full tile of compute.
//
// Permuted smem layouts (conflict-free, vectorized fragment loads):
//  K/Q: element (row, col) at (col%4)*KM_BLK + row*36 + col/4
//  V:   element (row, col) at (col%8)*VM_BLK + row*20 + col/8
// ---------------------------------------------------------------------------
#define KM_BLK  2312     // 64*36 + 8  (== 8 mod 32)
#define K_RS    36
#define VM_BLK  1296     // 64*20 + 16 (== 16 mod 32)
#define V_RS    20
#define PS_STRIDE 68
#define BQ      128
#define ATT_KS_U32 (4 * KM_BLK)
#define ATT_VS_U32 (8 * VM_BLK)
#define ATT_PS_U32 (BQ * PS_STRIDE)
#define ATT_SMEM_U32 (ATT_KS_U32 + ATT_VS_U32 + ATT_PS_U32)
#define ATT_SMEM_BYTES (ATT_SMEM_U32 * 4)

__global__ __launch_bounds__(256, 1)
void attn_tc_kernel(const float* __restrict__ qkv, float* __restrict__ z)
{
    extern __shared__ uint32_t sm[];
    uint32_t* Ks = sm;                       // K (and Q staging), k-residue layout
    uint32_t* Vs = sm + ATT_KS_U32;          // V, n-residue layout
    uint32_t* Ps = Vs + ATT_VS_U32;          // P, row-major stride 68 (128 rows)

    const int tid  = threadIdx.x;
    const int w    = tid >> 5;    // 0..7
    const int lane = tid & 31;
    const int g    = lane >> 2;   // 0..7
    const int tig  = lane & 3;    // 0..3

    const int qt = blockIdx.x;
    const int h  = blockIdx.y;
    const int b  = blockIdx.z;
    const int n0 = qt * BQ;

    const float scale = 0.08838834764831845f;   // 1/sqrt(128)

    const float* qbase = qkv + (size_t)(b * SEQ + n0) * QKVC + h * HDIM;
    const float* kbase = qkv + (size_t)(b * SEQ) * QKVC + INNER + h * HDIM;
    const float* vbase = kbase + INNER;

    const int r_lo = w * 16 + g;     // block-local q row (low half), 0..127

    // ---- stage Q (scaled, tf32) through Ks in two 64-row halves
    uint32_t qa[16][4];
#pragma unroll 1
    for (int half = 0; half < 2; half++) {
        for (int f = tid; f < 2048; f += 256) {
            int row = f >> 5;     // 0..63 within half
            int c4  = f & 31;
            float4 v = *reinterpret_cast<const float4*>(
                qbase + (size_t)(half * 64 + row) * QKVC + 4 * c4);
            int base = row * K_RS + c4;
            Ks[0 * KM_BLK + base] = f2tf32(v.x * scale);
            Ks[1 * KM_BLK + base] = f2tf32(v.y * scale);
            Ks[2 * KM_BLK + base] = f2tf32(v.z * scale);
            Ks[3 * KM_BLK + base] = f2tf32(v.w * scale);
        }
        __syncthreads();
        if ((w >> 2) == half) {
            const int rl = (w & 3) * 16 + g;   // row within this 64-row half
#pragma unroll
            for (int G = 0; G < 8; G++) {
                uint4 alo = *reinterpret_cast<const uint4*>(
                    &Ks[tig * KM_BLK + rl * K_RS + 4 * G]);
                uint4 ahi = *reinterpret_cast<const uint4*>(
                    &Ks[tig * KM_BLK + (rl + 8) * K_RS + 4 * G]);
                qa[2 * G][0]     = alo.x; qa[2 * G][1]     = ahi.x;
                qa[2 * G][2]     = alo.y; qa[2 * G][3]     = ahi.y;
                qa[2 * G + 1][0] = alo.z; qa[2 * G + 1][1] = ahi.z;
                qa[2 * G + 1][2] = alo.w; qa[2 * G + 1][3] = ahi.w;
            }
        }
        __syncthreads();
    }

    float oacc[16][4];
#pragma unroll
    for (int nf = 0; nf < 16; nf++)
#pragma unroll
        for (int c = 0; c < 4; c++) oacc[nf][c] = 0.0f;
    float m0 = -1e30f, m1 = -1e30f, l0 = 0.0f, l1 = 0.0f;

    // ---- prefetch tile 0 into registers (8 K-float4 + 8 V-float4 per thread)
    float4 kpre[8], vpre[8];
#pragma unroll
    for (int i = 0; i < 8; i++) {
        int f   = tid + i * 256;
        int row = f >> 5;
        int c4  = f & 31;
        kpre[i] = *reinterpret_cast<const float4*>(
            kbase + (size_t)row * QKVC + 4 * c4);
        vpre[i] = *reinterpret_cast<const float4*>(
            vbase + (size_t)row * QKVC + 4 * c4);
    }

#pragma unroll 1
    for (int j0 = 0; j0 < SEQ; j0 += 64) {
        __syncthreads();   // previous tile's smem reads complete
        // ---- STS prefetched K (k-residue) and V (n-residue), converting to tf32
#pragma unroll
        for (int i = 0; i < 8; i++) {
            int f   = tid + i * 256;
            int row = f >> 5;
            int c4  = f & 31;
            int kb = row * K_RS + c4;
            Ks[0 * KM_BLK + kb] = f2tf32(kpre[i].x);
            Ks[1 * KM_BLK + kb] = f2tf32(kpre[i].y);
            Ks[2 * KM_BLK + kb] = f2tf32(kpre[i].z);
            Ks[3 * KM_BLK + kb] = f2tf32(kpre[i].w);
            int vb  = row * V_RS + (c4 >> 1);
            int m8b = (c4 & 1) << 2;
            Vs[(m8b + 0) * VM_BLK + vb] = f2tf32(vpre[i].x);
            Vs[(m8b + 1) * VM_BLK + vb] = f2tf32(vpre[i].y);
            Vs[(m8b + 2) * VM_BLK + vb] = f2tf32(vpre[i].z);
            Vs[(m8b + 3) * VM_BLK + vb] = f2tf32(vpre[i].w);
        }
        __syncthreads();

        // ---- issue next tile's loads (latency hidden behind this tile's compute)
        if (j0 + 64 < SEQ) {
            const float* knext = kbase + (size_t)(j0 + 64) * QKVC;
            const float* vnext = vbase + (size_t)(j0 + 64) * QKVC;
#pragma unroll
            for (int i = 0; i < 8; i++) {
                int f   = tid + i * 256;
                int row = f >> 5;
                int c4  = f & 31;
                kpre[i] = *reinterpret_cast<const float4*>(
                    knext + (size_t)row * QKVC + 4 * c4);
                vpre[i] = *reinterpret_cast<const float4*>(
                    vnext + (size_t)row * QKVC + 4 * c4);
            }
        }

        // ---- S = Q @ K^T (16x64 per warp)
        float sacc[8][4];
#pragma unroll
        for (int nf = 0; nf < 8; nf++)
#pragma unroll
            for (int c = 0; c < 4; c++) sacc[nf][c] = 0.0f;

#pragma unroll
        for (int G = 0; G < 8; G++) {
#pragma unroll
            for (int nf = 0; nf < 8; nf++) {
                uint4 kb = *reinterpret_cast<const uint4*>(
                    &Ks[tig * KM_BLK + (nf * 8 + g) * K_RS + 4 * G]);
                mma_tf32(sacc[nf], qa[2 * G], kb.x, kb.y);
                mma_tf32(sacc[nf], qa[2 * G + 1], kb.z, kb.w);
            }
        }

        // ---- online softmax (rows r_lo via c0/c1, r_lo+8 via c2/c3)
        float rm0 = -1e30f, rm1 = -1e30f;
#pragma unroll
        for (int nf = 0; nf < 8; nf++) {
            rm0 = fmaxf(rm0, fmaxf(sacc[nf][0], sacc[nf][1]));
            rm1 = fmaxf(rm1, fmaxf(sacc[nf][2], sacc[nf][3]));
        }
        rm0 = fmaxf(rm0, __shfl_xor_sync(0xffffffffu, rm0, 1));
        rm0 = fmaxf(rm0, __shfl_xor_sync(0xffffffffu, rm0, 2));
        rm1 = fmaxf(rm1, __shfl_xor_sync(0xffffffffu, rm1, 1));
        rm1 = fmaxf(rm1, __shfl_xor_sync(0xffffffffu, rm1, 2));

        float mn0 = fmaxf(m0, rm0);
        float mn1 = fmaxf(m1, rm1);
        float al0 = __expf(m0 - mn0);
        float al1 = __expf(m1 - mn1);
        float rs0 = 0.0f, rs1 = 0.0f;
#pragma unroll
        for (int nf = 0; nf < 8; nf++) {
            float p0 = __expf(sacc[nf][0] - mn0);
            float p1 = __expf(sacc[nf][1] - mn0);
            float p2 = __expf(sacc[nf][2] - mn1);
            float p3 = __expf(sacc[nf][3] - mn1);
            rs0 += p0 + p1;
            rs1 += p2 + p3;
            Ps[r_lo * PS_STRIDE + nf * 8 + 2 * tig]     = f2tf32(p0);
            Ps[r_lo * PS_STRIDE + nf * 8 + 2 * tig + 1] = f2tf32(p1);
            Ps[(r_lo + 8) * PS_STRIDE + nf * 8 + 2 * tig]     = f2tf32(p2);
            Ps[(r_lo + 8) * PS_STRIDE + nf * 8 + 2 * tig + 1] = f2tf32(p3);
        }
        rs0 += __shfl_xor_sync(0xffffffffu, rs0, 1);
        rs0 += __shfl_xor_sync(0xffffffffu, rs0, 2);
        rs1 += __shfl_xor_sync(0xffffffffu, rs1, 1);
        rs1 += __shfl_xor_sync(0xffffffffu, rs1, 2);
        l0 = al0 * l0 + rs0;
        l1 = al1 * l1 + rs1;
        m0 = mn0;
        m1 = mn1;
#pragma unroll
        for (int nf = 0; nf < 16; nf++) {
            oacc[nf][0] *= al0;
            oacc[nf][1] *= al0;
            oacc[nf][2] *= al1;
            oacc[nf][3] *= al1;
        }
        __syncwarp();   // Ps visibility within warp

        // ---- O += P @ V (16x128 per warp)
#pragma unroll
        for (int ks = 0; ks < 8; ks++) {
            uint32_t pa[4];
            pa[0] = Ps[r_lo * PS_STRIDE + ks * 8 + tig];
            pa[1] = Ps[(r_lo + 8) * PS_STRIDE + ks * 8 + tig];
            pa[2] = Ps[r_lo * PS_STRIDE + ks * 8 + tig + 4];
            pa[3] = Ps[(r_lo + 8) * PS_STRIDE + ks * 8 + tig + 4];
#pragma unroll
            for (int Gv = 0; Gv < 4; Gv++) {
                uint4 v0 = *reinterpret_cast<const uint4*>(
                    &Vs[g * VM_BLK + (8 * ks + tig) * V_RS + 4 * Gv]);
                uint4 v1 = *reinterpret_cast<const uint4*>(
                    &Vs[g * VM_BLK + (8 * ks + tig + 4) * V_RS + 4 * Gv]);
                mma_tf32(oacc[4 * Gv + 0], pa, v0.x, v1.x);
                mma_tf32(oacc[4 * Gv + 1], pa, v0.y, v1.y);
                mma_tf32(oacc[4 * Gv + 2], pa, v0.z, v1.z);
                mma_tf32(oacc[4 * Gv + 3], pa, v0.w, v1.w);
            }
        }
    }

    // ---- normalize + write z
    float inv0 = 1.0f / l0;
    float inv1 = 1.0f / l1;
    const size_t row0 = (size_t)(b * SEQ + n0 + r_lo);
    const size_t row1 = row0 + 8;
#pragma unroll
    for (int nf = 0; nf < 16; nf++) {
        int col = h * HDIM + nf * 8 + 2 * tig;
        float2 lo = make_float2(oacc[nf][0] * inv0, oacc[nf][1] * inv0);
        float2 hi = make_float2(oacc[nf][2] * inv1, oacc[nf][3] * inv1);
        *reinterpret_cast<float2*>(z + row0 * INNER + col) = lo;
        *reinterpret_cast<float2*>(z + row1 * INNER + col) = hi;
    }
}

// ---------------------------------------------------------------------------
// Launch
// ---------------------------------------------------------------------------
extern "C" void kernel_launch(void* const* d_in, const int* in_sizes, int n_in,
                              void* d_out, int out_size)
{
    const float* x     = (const float*)d_in[0];   // [8,1024,128]
    const float* w_qkv = (const float*)d_in[1];   // [128,3072]
    const float* w_out = (const float*)d_in[2];   // [1024,128]
    const float* b_out = (const float*)d_in[3];   // [128]
    float* out = (float*)d_out;                   // [8,1024,128]

    void* qkvp = nullptr;
    void* zp   = nullptr;
    cudaGetSymbolAddress(&qkvp, g_qkv);
    cudaGetSymbolAddress(&zp, g_z);
    float* qkv = (float*)qkvp;
    float* zb  = (float*)zp;

    // 1) QKV projection: [8192,128] @ [128,3072] (tf32, 8 warps/block)
    {
        dim3 grid(QKVC / 128, NTOK / 128);
        tf32_gemm_kernel<128, 128, 32, 64, 32, false><<<grid, 256>>>(
            x, w_qkv, qkv, nullptr, NTOK, QKVC, DMODEL);
    }

    // 2) attention (tf32 tensor cores, prefetch double buffering, BQ=128)
    {
        cudaFuncSetAttribute(attn_tc_kernel,
                             cudaFuncAttributeMaxDynamicSharedMemorySize,
                             ATT_SMEM_BYTES);
        dim3 grid(SEQ / BQ, NHEADS, BATCH);
        attn_tc_kernel<<<grid, 256, ATT_SMEM_BYTES>>>(qkv, zb);
    }

    // 3) output projection: [8192,1024] @ [1024,128] + bias (tf32)
    {
        dim3 grid(DMODEL / 128, NTOK / 32);
        tf32_gemm_kernel<32, 128, 64, 16, 64, true><<<grid, 128>>>(
            zb, w_out, out, b_out, NTOK, DMODEL, INNER);
    }
}